// round 14
// baseline (speedup 1.0000x reference)
#include <cuda_runtime.h>
#include <cuda_bf16.h>
#include <math.h>
#include <stdint.h>

#define BATCH   2
#define SEQ     2048
#define EMBED   1024
#define HEADS   16
#define HDIM    64
#define HIDDEN  4096
#define MTOT    (BATCH * SEQ)
#define QKVN    3072
#define LN_EPS  1e-5f
#define NROWS   (BATCH * HEADS * SEQ)
#define NTILES  (SEQ / 128)

// ------------------------- scratch (device globals) -------------------------
__device__ __nv_bfloat16 g_xh [MTOT*EMBED], g_xl [MTOT*EMBED];
__device__ __nv_bfloat16 g_qkvh[(size_t)MTOT*QKVN], g_qkvl[(size_t)MTOT*QKVN];
__device__ __nv_bfloat16 g_vT_h[(size_t)BATCH*EMBED*SEQ], g_vT_l[(size_t)BATCH*EMBED*SEQ];
__device__ __nv_bfloat16 g_aoh[MTOT*EMBED], g_aol[MTOT*EMBED];
__device__ float         g_t1 [MTOT*EMBED];
__device__ float         g_h  [MTOT*EMBED];
__device__ __nv_bfloat16 g_hh [MTOT*EMBED], g_hl [MTOT*EMBED];
__device__ __nv_bfloat16 g_hidh[(size_t)MTOT*HIDDEN], g_hidl[(size_t)MTOT*HIDDEN];
__device__ float         g_mlp[MTOT*EMBED];
__device__ float2        g_pstats[(size_t)NROWS * NTILES];
__device__ float2        g_rstats[NROWS];
__device__ float         g_bqkv[QKVN];

__device__ __nv_bfloat16 g_wqkv_h[(size_t)QKVN*EMBED], g_wqkv_l[(size_t)QKVN*EMBED];
__device__ __nv_bfloat16 g_wo_h[EMBED*EMBED], g_wo_l[EMBED*EMBED];
__device__ __nv_bfloat16 g_w1_h[(size_t)EMBED*HIDDEN], g_w1_l[(size_t)EMBED*HIDDEN];
__device__ __nv_bfloat16 g_w2_h[(size_t)EMBED*HIDDEN], g_w2_l[(size_t)EMBED*HIDDEN];

// ------------------------------- helpers ------------------------------------
__device__ __forceinline__ uint32_t smem_u32(const void* p) {
    uint32_t a;
    asm("{ .reg .u64 t; cvta.to.shared.u64 t, %1; cvt.u32.u64 %0, t; }" : "=r"(a) : "l"(p));
    return a;
}
__device__ __forceinline__ uint32_t sw_off(int row, int kb) {
    uint32_t o = ((uint32_t)(row >> 3) << 10) + ((uint32_t)(row & 7) << 7) + (uint32_t)kb;
    return o ^ ((o >> 3) & 0x70);
}
__device__ __forceinline__ void ldm_x4(uint32_t* r, uint32_t a) {
    asm volatile("ldmatrix.sync.aligned.m8n8.x4.shared.b16 {%0,%1,%2,%3}, [%4];"
                 : "=r"(r[0]), "=r"(r[1]), "=r"(r[2]), "=r"(r[3]) : "r"(a));
}
__device__ __forceinline__ void mma_bf16(float* c, const uint32_t* a, const uint32_t* b) {
    asm volatile("mma.sync.aligned.m16n8k16.row.col.f32.bf16.bf16.f32 "
                 "{%0,%1,%2,%3}, {%4,%5,%6,%7}, {%8,%9}, {%0,%1,%2,%3};"
                 : "+f"(c[0]), "+f"(c[1]), "+f"(c[2]), "+f"(c[3])
                 : "r"(a[0]), "r"(a[1]), "r"(a[2]), "r"(a[3]), "r"(b[0]), "r"(b[1]));
}
__device__ __forceinline__ void cp_async16(uint32_t dst, const void* src) {
    asm volatile("cp.async.ca.shared.global [%0], [%1], 16;" :: "r"(dst), "l"(src) : "memory");
}
#define CP_COMMIT() asm volatile("cp.async.commit_group;" ::: "memory")
#define CP_WAIT2()  asm volatile("cp.async.wait_group 2;" ::: "memory")
#define CP_WAIT0()  asm volatile("cp.async.wait_group 0;" ::: "memory")

__device__ __forceinline__ float gelu_exact(float x) {
    return 0.5f * x * (1.0f + erff(x * 0.70710678118654752f));
}
__device__ __forceinline__ uint32_t b2u(__nv_bfloat162 h) { return *(uint32_t*)&h; }
__device__ __forceinline__ void split2(float v0, float v1,
                                       __nv_bfloat162& h, __nv_bfloat162& l) {
    h = __floats2bfloat162_rn(v0, v1);
    float2 f = __bfloat1622float2(h);
    l = __floats2bfloat162_rn(v0 - f.x, v1 - f.y);
}

// ---------------------------------------------------------------------------
// Pure-async bf16x3 warp-tiled GEMM (128x128): C = act(alpha*A@B^T + bias)
// ---------------------------------------------------------------------------
template <bool STATS>
__global__ void __launch_bounds__(256, 1)
gemm_bb(int K,
        const __nv_bfloat16* __restrict__ Ah, const __nv_bfloat16* __restrict__ Al, int lda,
        const __nv_bfloat16* __restrict__ Bh, const __nv_bfloat16* __restrict__ Bl, int ldb,
        float* __restrict__ Cf, __nv_bfloat16* __restrict__ Ch,
        __nv_bfloat16* __restrict__ Cl, int ldc,
        const float* __restrict__ bias, float alpha, int act,
        long long sAb, long long sAh, long long sBb, long long sBh,
        long long sCb, long long sCh, int Hn,
        float2* __restrict__ pstats)
{
    constexpr int BG  = 128 * 128;
    constexpr int STG = 32768 + 2 * BG;
    constexpr int MF  = 4, NF = 4;

    extern __shared__ char smem[];
    const uint32_t sm32 = smem_u32(smem);
    const int tid = threadIdx.x, wid = tid >> 5, lane = tid & 31;
    const int warp_m = wid >> 2, warp_n = wid & 3;
    const int wm0 = warp_m * 64, wn0 = warp_n * 32;

    const int bn = blockIdx.x * 128, bm = blockIdx.y * 128;
    const int bb = blockIdx.z / Hn, hh = blockIdx.z % Hn;
    {
        long long oa = (long long)bb * sAb + (long long)hh * sAh + (long long)bm * lda;
        long long ob = (long long)bb * sBb + (long long)hh * sBh + (long long)bn * ldb;
        Ah += oa; Al += oa; Bh += ob; Bl += ob;
    }
    const long long oc = (long long)bb * sCb + (long long)hh * sCh;
    if (Cf) Cf += oc;
    if (Ch) { Ch += oc; Cl += oc; }

    const int NC = K >> 6;
    const int a_r = lane & 15, a_k16 = (lane >> 4) << 4;
    const int b_row = lane & 7, b_nb = (lane >> 4) & 1, b_k16 = ((lane >> 3) & 1) << 4;

    float acc[MF][NF][4];
#pragma unroll
    for (int mi = 0; mi < MF; mi++)
#pragma unroll
        for (int ni = 0; ni < NF; ni++)
#pragma unroll
            for (int e = 0; e < 4; e++) acc[mi][ni][e] = 0.f;

    auto issue = [&](int c, int s) {
        const int k0 = c << 6;
        const uint32_t st = sm32 + s * STG;
#pragma unroll
        for (int it = 0; it < 4; it++) {
            int id = it * 256 + tid;
            int row = id >> 3, u = id & 7;
            uint32_t o = sw_off(row, u * 16);
            const size_t sidx = (size_t)row * lda + k0 + u * 8;
            cp_async16(st + o,         Ah + sidx);
            cp_async16(st + 16384 + o, Al + sidx);
        }
#pragma unroll
        for (int it = 0; it < 4; it++) {
            int id = it * 256 + tid;
            int row = id >> 3, u = id & 7;
            uint32_t o = sw_off(row, u * 16);
            const size_t sidx = (size_t)row * ldb + k0 + u * 8;
            cp_async16(st + 32768 + o,      Bh + sidx);
            cp_async16(st + 32768 + BG + o, Bl + sidx);
        }
    };

#pragma unroll
    for (int s = 0; s < 2; s++) {
        if (s < NC) issue(s, s);
        CP_COMMIT();
    }

    for (int c = 0; c < NC; c++) {
        if (c + 2 < NC) issue(c + 2, (c + 2) % 3);
        CP_COMMIT();
        CP_WAIT2();
        __syncthreads();

        const uint32_t sA = sm32 + (c % 3) * STG;
        const uint32_t sB = sA + 32768;
#pragma unroll
        for (int ks = 0; ks < 4; ks++) {
            uint32_t ah[MF][4], al[MF][4], bh[NF][2], bl[NF][2];
#pragma unroll
            for (int mi = 0; mi < MF; mi++) {
                uint32_t off = sw_off(wm0 + mi * 16 + a_r, ks * 32 + a_k16);
                ldm_x4(ah[mi], sA + off);
                ldm_x4(al[mi], sA + 16384 + off);
            }
#pragma unroll
            for (int ni = 0; ni < NF; ni += 2) {
                uint32_t off = sw_off(wn0 + (ni + b_nb) * 8 + b_row, ks * 32 + b_k16);
                uint32_t r[4];
                ldm_x4(r, sB + off);
                bh[ni][0] = r[0]; bh[ni][1] = r[1];
                bh[ni+1][0] = r[2]; bh[ni+1][1] = r[3];
                ldm_x4(r, sB + BG + off);
                bl[ni][0] = r[0]; bl[ni][1] = r[1];
                bl[ni+1][0] = r[2]; bl[ni+1][1] = r[3];
            }
#pragma unroll
            for (int mi = 0; mi < MF; mi++)
#pragma unroll
                for (int ni = 0; ni < NF; ni++) {
                    mma_bf16(acc[mi][ni], ah[mi], bh[ni]);
                    mma_bf16(acc[mi][ni], ah[mi], bl[ni]);
                    mma_bf16(acc[mi][ni], al[mi], bh[ni]);
                }
        }
        __syncthreads();
    }

    // ---- standard epilogue ----
#pragma unroll
    for (int mi = 0; mi < MF; mi++) {
        const int r0 = bm + wm0 + mi * 16 + (lane >> 2);
#pragma unroll
        for (int ni = 0; ni < NF; ni++) {
            const int cb = bn + wn0 + ni * 8 + (lane & 3) * 2;
            const float b0 = bias ? bias[cb] : 0.f, b1 = bias ? bias[cb + 1] : 0.f;
            float v0 = acc[mi][ni][0] * alpha + b0;
            float v1 = acc[mi][ni][1] * alpha + b1;
            float v2 = acc[mi][ni][2] * alpha + b0;
            float v3 = acc[mi][ni][3] * alpha + b1;
            if (act) { v0 = gelu_exact(v0); v1 = gelu_exact(v1);
                       v2 = gelu_exact(v2); v3 = gelu_exact(v3); }
            const size_t i0 = (size_t)r0 * ldc + cb;
            const size_t i1 = (size_t)(r0 + 8) * ldc + cb;
            if (Cf) {
                *(float2*)(Cf + i0) = make_float2(v0, v1);
                *(float2*)(Cf + i1) = make_float2(v2, v3);
            }
            if (Ch) {
                __nv_bfloat162 h, l;
                split2(v0, v1, h, l);
                *(__nv_bfloat162*)(Ch + i0) = h;
                *(__nv_bfloat162*)(Cl + i0) = l;
                split2(v2, v3, h, l);
                *(__nv_bfloat162*)(Ch + i1) = h;
                *(__nv_bfloat162*)(Cl + i1) = l;
            }
        }
    }

    if constexpr (STATS) {
        float* smaxw = (float*)smem;
        float* ssumw = (float*)smem + 512;
        float* rowmx = (float*)smem + 1024;
#pragma unroll
        for (int mi = 0; mi < MF; mi++)
#pragma unroll
            for (int rr = 0; rr < 2; rr++) {
                int row = wm0 + mi * 16 + (lane >> 2) + rr * 8;
                float mx = -1e30f;
#pragma unroll
                for (int ni = 0; ni < NF; ni++) {
                    mx = fmaxf(mx, acc[mi][ni][rr * 2]     * alpha);
                    mx = fmaxf(mx, acc[mi][ni][rr * 2 + 1] * alpha);
                }
                mx = fmaxf(mx, __shfl_xor_sync(0xffffffffu, mx, 1));
                mx = fmaxf(mx, __shfl_xor_sync(0xffffffffu, mx, 2));
                if ((lane & 3) == 0) smaxw[warp_n * 128 + row] = mx;
            }
        __syncthreads();
        if (tid < 128) {
            float m = fmaxf(fmaxf(smaxw[tid], smaxw[128 + tid]),
                            fmaxf(smaxw[256 + tid], smaxw[384 + tid]));
            rowmx[tid] = m;
        }
        __syncthreads();
#pragma unroll
        for (int mi = 0; mi < MF; mi++)
#pragma unroll
            for (int rr = 0; rr < 2; rr++) {
                int row = wm0 + mi * 16 + (lane >> 2) + rr * 8;
                float m = rowmx[row], s = 0.f;
#pragma unroll
                for (int ni = 0; ni < NF; ni++) {
                    s += __expf(acc[mi][ni][rr * 2]     * alpha - m);
                    s += __expf(acc[mi][ni][rr * 2 + 1] * alpha - m);
                }
                s += __shfl_xor_sync(0xffffffffu, s, 1);
                s += __shfl_xor_sync(0xffffffffu, s, 2);
                if ((lane & 3) == 0) ssumw[warp_n * 128 + row] = s;
            }
        __syncthreads();
        if (tid < 128) {
            float s = ssumw[tid] + ssumw[128 + tid] + ssumw[256 + tid] + ssumw[384 + tid];
            pstats[((long long)blockIdx.z * SEQ + bm + tid) * NTILES + blockIdx.x] =
                make_float2(rowmx[tid], s);
        }
    }
}

// ---- combine per-tile stats -> per-row (M, 1/S) -----------------------------
__global__ void __launch_bounds__(256)
combine_stats(const float2* __restrict__ ps, float2* __restrict__ rs)
{
    int r = blockIdx.x * 256 + threadIdx.x;
    if (r >= NROWS) return;
    const float2* p = ps + (size_t)r * NTILES;
    float M = -1e30f;
    float2 t[NTILES];
#pragma unroll
    for (int i = 0; i < NTILES; i++) { t[i] = p[i]; M = fmaxf(M, t[i].x); }
    float S = 0.f;
#pragma unroll
    for (int i = 0; i < NTILES; i++) S += t[i].y * __expf(t[i].x - M);
    rs[r] = make_float2(M, 1.0f / S);
}

// ---------------------------------------------------------------------------
// Fused softmax-apply + P@V (2 CTAs/SM).  Reads E fp32, writes P in place,
// ao = P @ vT^T -> bf16 hi/lo.  grid (1, SEQ/128, B*H).
// ---------------------------------------------------------------------------
__global__ void __launch_bounds__(256, 2)
gemm_pv(float* __restrict__ E_all, const float2* __restrict__ rs_all,
        const __nv_bfloat16* __restrict__ Vh_all, const __nv_bfloat16* __restrict__ Vl_all,
        __nv_bfloat16* __restrict__ Ch_all, __nv_bfloat16* __restrict__ Cl_all)
{
    constexpr int AG = 16384, ASZ = 32768, BG = 8192, BUF = ASZ + 2 * BG;
    constexpr int MF = 2, NF = 4;

    extern __shared__ char smem[];
    const uint32_t sm32 = smem_u32(smem);
    const int tid = threadIdx.x, wid = tid >> 5, lane = tid & 31;
    const int warp_m = wid >> 1, warp_n = wid & 1;
    const int wm0 = warp_m * 32, wn0 = warp_n * 32;

    const int bm = blockIdx.y * 128;
    const int z = blockIdx.z, bb = z >> 4, hh = z & 15;
    float* E = E_all + (long long)z * SEQ * SEQ + (long long)bm * SEQ;
    const float2* rs = rs_all + (long long)z * SEQ + bm;
    const size_t vo = (size_t)bb * EMBED * SEQ + (size_t)hh * HDIM * SEQ;
    const __nv_bfloat16* Bh = Vh_all + vo;
    const __nv_bfloat16* Bl = Vl_all + vo;

    float2 ms[8];
#pragma unroll
    for (int it = 0; it < 8; it++) ms[it] = rs[(it * 256 + tid) >> 4];

    const int a_r = lane & 15, a_k16 = (lane >> 4) << 4;
    const int b_row = lane & 7, b_nb = (lane >> 4) & 1, b_k16 = ((lane >> 3) & 1) << 4;

    float acc[MF][NF][4];
#pragma unroll
    for (int mi = 0; mi < MF; mi++)
#pragma unroll
        for (int ni = 0; ni < NF; ni++)
#pragma unroll
            for (int e = 0; e < 4; e++) acc[mi][ni][e] = 0.f;

    auto issueB = [&](int c, int s) {
        const int k0 = c << 6;
        const uint32_t st = sm32 + s * BUF + ASZ;
#pragma unroll
        for (int it = 0; it < 2; it++) {
            int id = it * 256 + tid;
            int row = id >> 3, u = id & 7;
            uint32_t o = sw_off(row, u * 16);
            const size_t sidx = (size_t)row * SEQ + k0 + u * 8;
            cp_async16(st + o,      Bh + sidx);
            cp_async16(st + BG + o, Bl + sidx);
        }
    };
    auto stageA = [&](int k0, char* dst) {
#pragma unroll
        for (int it = 0; it < 8; it++) {
            int id = it * 256 + tid;
            int row = id >> 4, c4 = (id & 15) << 2;
            float4 e = *(const float4*)(E + (size_t)row * SEQ + k0 + c4);
            const float M = ms[it].x, IS = ms[it].y;
            float4 p;
            p.x = __expf(e.x - M) * IS;
            p.y = __expf(e.y - M) * IS;
            p.z = __expf(e.z - M) * IS;
            p.w = __expf(e.w - M) * IS;
            *(float4*)(E + (size_t)row * SEQ + k0 + c4) = p;
            __nv_bfloat162 h0, l0, h1, l1;
            split2(p.x, p.y, h0, l0);
            split2(p.z, p.w, h1, l1);
            uint32_t off = sw_off(row, c4 * 2);
            *(uint2*)(dst + off)      = make_uint2(b2u(h0), b2u(h1));
            *(uint2*)(dst + AG + off) = make_uint2(b2u(l0), b2u(l1));
        }
    };

    issueB(0, 0);
    CP_COMMIT();
    stageA(0, smem);
    CP_WAIT0();
    __syncthreads();

    constexpr int NC = SEQ >> 6;
    for (int c = 0; c < NC; c++) {
        const int buf = c & 1;
        char* nxt = smem + (buf ^ 1) * BUF;
        const bool more = (c + 1 < NC);

        if (more) { issueB(c + 1, buf ^ 1); CP_COMMIT(); }

        const uint32_t sA = sm32 + buf * BUF;
        const uint32_t sB = sA + ASZ;
#pragma unroll
        for (int ks = 0; ks < 4; ks++) {
            uint32_t ah[MF][4], al[MF][4], bh[NF][2], bl[NF][2];
#pragma unroll
            for (int mi = 0; mi < MF; mi++) {
                uint32_t off = sw_off(wm0 + mi * 16 + a_r, ks * 32 + a_k16);
                ldm_x4(ah[mi], sA + off);
                ldm_x4(al[mi], sA + AG + off);
            }
#pragma unroll
            for (int ni = 0; ni < NF; ni += 2) {
                uint32_t off = sw_off(wn0 + (ni + b_nb) * 8 + b_row, ks * 32 + b_k16);
                uint32_t r[4];
                ldm_x4(r, sB + off);
                bh[ni][0] = r[0]; bh[ni][1] = r[1];
                bh[ni+1][0] = r[2]; bh[ni+1][1] = r[3];
                ldm_x4(r, sB + BG + off);
                bl[ni][0] = r[0]; bl[ni][1] = r[1];
                bl[ni+1][0] = r[2]; bl[ni+1][1] = r[3];
            }
#pragma unroll
            for (int mi = 0; mi < MF; mi++)
#pragma unroll
                for (int ni = 0; ni < NF; ni++) {
                    mma_bf16(acc[mi][ni], ah[mi], bh[ni]);
                    mma_bf16(acc[mi][ni], ah[mi], bl[ni]);
                    mma_bf16(acc[mi][ni], al[mi], bh[ni]);
                }
        }

        if (more) {
            stageA((c + 1) << 6, nxt);
            CP_WAIT0();
        }
        __syncthreads();
    }

#pragma unroll
    for (int mi = 0; mi < MF; mi++) {
        const int gr = bm + wm0 + mi * 16 + (lane >> 2);
#pragma unroll
        for (int ni = 0; ni < NF; ni++) {
            const int cb = wn0 + ni * 8 + (lane & 3) * 2;
            const size_t i0 = ((size_t)bb * SEQ + gr)     * EMBED + hh * HDIM + cb;
            const size_t i1 = ((size_t)bb * SEQ + gr + 8) * EMBED + hh * HDIM + cb;
            __nv_bfloat162 h, l;
            split2(acc[mi][ni][0], acc[mi][ni][1], h, l);
            *(__nv_bfloat162*)(Ch_all + i0) = h;
            *(__nv_bfloat162*)(Cl_all + i0) = l;
            split2(acc[mi][ni][2], acc[mi][ni][3], h, l);
            *(__nv_bfloat162*)(Ch_all + i1) = h;
            *(__nv_bfloat162*)(Cl_all + i1) = l;
        }
    }
}

// -------- transpose + split:  in [K][N] fp32  ->  out [N][K] bf16 hi/lo -----
__global__ void __launch_bounds__(256)
transpose_split(const float* __restrict__ in, int K, int N,
                __nv_bfloat16* __restrict__ oh, __nv_bfloat16* __restrict__ ol)
{
    __shared__ float tb[32][33];
    const int n0 = blockIdx.x * 32, k0 = blockIdx.y * 32;
    const int tx = threadIdx.x & 31, ty = threadIdx.x >> 5;
    for (int j = ty; j < 32; j += 8)
        tb[j][tx] = in[(size_t)(k0 + j) * N + n0 + tx];
    __syncthreads();
    for (int j = ty; j < 32; j += 8) {
        float v = tb[tx][j];
        __nv_bfloat16 h = __float2bfloat16(v);
        __nv_bfloat16 l = __float2bfloat16(v - __bfloat162float(h));
        size_t o = (size_t)(n0 + j) * K + k0 + tx;
        oh[o] = h; ol[o] = l;
    }
}

// -------- vT from fused qkv hi/lo: [b][s][3072] cols 2048+ -> [b][d][s] ------
__global__ void __launch_bounds__(256)
transpose_split_hl(const __nv_bfloat16* __restrict__ inh,
                   const __nv_bfloat16* __restrict__ inl,
                   __nv_bfloat16* __restrict__ oh, __nv_bfloat16* __restrict__ ol)
{
    __shared__ float tb[32][33];
    const int d0 = blockIdx.x * 32, s0 = blockIdx.y * 32, b = blockIdx.z;
    const int tx = threadIdx.x & 31, ty = threadIdx.x >> 5;
    for (int j = ty; j < 32; j += 8) {
        size_t idx = ((size_t)(b * SEQ + s0 + j)) * QKVN + 2048 + d0 + tx;
        tb[j][tx] = __bfloat162float(inh[idx]) + __bfloat162float(inl[idx]);
    }
    __syncthreads();
    for (int j = ty; j < 32; j += 8) {
        float v = tb[tx][j];
        __nv_bfloat16 h = __float2bfloat16(v);
        __nv_bfloat16 l = __float2bfloat16(v - __bfloat162float(h));
        size_t o = ((size_t)b * EMBED + d0 + j) * SEQ + s0 + tx;
        oh[o] = h; ol[o] = l;
    }
}

// -------- elementwise split + bias concat ------------------------------------
__global__ void __launch_bounds__(256)
split_f32(const float* __restrict__ in,
          __nv_bfloat16* __restrict__ oh, __nv_bfloat16* __restrict__ ol, int n4)
{
    int i = blockIdx.x * 256 + threadIdx.x;
    if (i >= n4) return;
    float4 v = ((const float4*)in)[i];
    __nv_bfloat162 h0, l0, h1, l1;
    split2(v.x, v.y, h0, l0);
    split2(v.z, v.w, h1, l1);
    ((__nv_bfloat162*)oh)[2*i]   = h0; ((__nv_bfloat162*)oh)[2*i+1] = h1;
    ((__nv_bfloat162*)ol)[2*i]   = l0; ((__nv_bfloat162*)ol)[2*i+1] = l1;
}
__global__ void __launch_bounds__(256)
concat_bias(const float* __restrict__ a, const float* __restrict__ b,
            const float* __restrict__ c, float* __restrict__ o)
{
    int i = blockIdx.x * 256 + threadIdx.x;
    if (i >= QKVN) return;
    o[i] = (i < 1024) ? a[i] : (i < 2048) ? b[i - 1024] : c[i - 2048];
}

// ------------------------------ add + LN ------------------------------------
__global__ void __launch_bounds__(256)
add_ln_kernel(const float* __restrict__ a, const float* __restrict__ b,
              const float* __restrict__ gamma, const float* __restrict__ beta,
              float* __restrict__ out,
              __nv_bfloat16* __restrict__ oh, __nv_bfloat16* __restrict__ ol)
{
    const long long base = (long long)blockIdx.x * EMBED;
    const int tid = threadIdx.x, lane = tid & 31, wid = tid >> 5;
    float v[4], s1 = 0.f, s2 = 0.f;
#pragma unroll
    for (int i = 0; i < 4; i++) {
        int col = i * 256 + tid;
        float x = a[base + col] + b[base + col];
        v[i] = x; s1 += x; s2 += x * x;
    }
#pragma unroll
    for (int o = 16; o; o >>= 1) {
        s1 += __shfl_xor_sync(0xffffffffu, s1, o);
        s2 += __shfl_xor_sync(0xffffffffu, s2, o);
    }
    __shared__ float r1[8], r2[8];
    if (lane == 0) { r1[wid] = s1; r2[wid] = s2; }
    __syncthreads();
    float t1 = 0.f, t2 = 0.f;
#pragma unroll
    for (int i = 0; i < 8; i++) { t1 += r1[i]; t2 += r2[i]; }
    float mu = t1 * (1.0f / EMBED);
    float var = t2 * (1.0f / EMBED) - mu * mu;
    float inv = rsqrtf(var + LN_EPS);
#pragma unroll
    for (int i = 0; i < 4; i++) {
        int col = i * 256 + tid;
        float y = (v[i] - mu) * inv * gamma[col] + beta[col];
        out[base + col] = y;
        if (oh) {
            __nv_bfloat16 h = __float2bfloat16(y);
            oh[base + col] = h;
            ol[base + col] = __float2bfloat16(y - __bfloat162float(h));
        }
    }
}

// ------------------------------- launcher -----------------------------------
extern "C" void kernel_launch(void* const* d_in, const int* in_sizes, int n_in,
                              void* d_out, int out_size)
{
    const float* x  = (const float*)d_in[0];
    const float* Wq = (const float*)d_in[1];  const float* bq = (const float*)d_in[2];
    const float* Wk = (const float*)d_in[3];  const float* bk = (const float*)d_in[4];
    const float* Wv = (const float*)d_in[5];  const float* bv = (const float*)d_in[6];
    const float* Wo = (const float*)d_in[7];  const float* bo = (const float*)d_in[8];
    const float* W1 = (const float*)d_in[9];  const float* b1 = (const float*)d_in[10];
    const float* W2 = (const float*)d_in[11]; const float* b2 = (const float*)d_in[12];
    const float* gamma = (const float*)d_in[13];
    const float* beta  = (const float*)d_in[14];

    float* out  = (float*)d_out;
    float* attn = out + (long long)MTOT * EMBED;

    float *t1, *h, *mlp, *bqkv;
    cudaGetSymbolAddress((void**)&t1,  g_t1);
    cudaGetSymbolAddress((void**)&h,   g_h);
    cudaGetSymbolAddress((void**)&mlp, g_mlp);
    cudaGetSymbolAddress((void**)&bqkv, g_bqkv);

    float2 *pst, *rst;
    cudaGetSymbolAddress((void**)&pst, g_pstats);
    cudaGetSymbolAddress((void**)&rst, g_rstats);

    __nv_bfloat16 *xh,*xl,*qkvh,*qkvl,*vth,*vtl,*aoh,*aol,*hh,*hl,*hidh,*hidl;
    cudaGetSymbolAddress((void**)&xh,  g_xh);  cudaGetSymbolAddress((void**)&xl,  g_xl);
    cudaGetSymbolAddress((void**)&qkvh,g_qkvh);cudaGetSymbolAddress((void**)&qkvl,g_qkvl);
    cudaGetSymbolAddress((void**)&vth, g_vT_h);cudaGetSymbolAddress((void**)&vtl, g_vT_l);
    cudaGetSymbolAddress((void**)&aoh, g_aoh); cudaGetSymbolAddress((void**)&aol, g_aol);
    cudaGetSymbolAddress((void**)&hh,  g_hh);  cudaGetSymbolAddress((void**)&hl,  g_hl);
    cudaGetSymbolAddress((void**)&hidh,g_hidh);cudaGetSymbolAddress((void**)&hidl,g_hidl);

    __nv_bfloat16 *wqkvh,*wqkvl,*woh,*wol,*w1h,*w1l,*w2h,*w2l;
    cudaGetSymbolAddress((void**)&wqkvh, g_wqkv_h); cudaGetSymbolAddress((void**)&wqkvl, g_wqkv_l);
    cudaGetSymbolAddress((void**)&woh, g_wo_h); cudaGetSymbolAddress((void**)&wol, g_wo_l);
    cudaGetSymbolAddress((void**)&w1h, g_w1_h); cudaGetSymbolAddress((void**)&w1l, g_w1_l);
    cudaGetSymbolAddress((void**)&w2h, g_w2_h); cudaGetSymbolAddress((void**)&w2l, g_w2_l);

    const int SMBB = 3 * (32768 + 2 * 128 * 128);         // 196608
    const int SMPV = 2 * (32768 + 2 * 64 * 128);          // 98304
    cudaFuncSetAttribute(gemm_bb<false>, cudaFuncAttributeMaxDynamicSharedMemorySize, SMBB);
    cudaFuncSetAttribute(gemm_bb<true>,  cudaFuncAttributeMaxDynamicSharedMemorySize, SMBB);
    cudaFuncSetAttribute(gemm_pv,        cudaFuncAttributeMaxDynamicSharedMemorySize, SMPV);

    const long long SS  = (long long)SEQ * SEQ;
    const long long SDQ = (long long)SEQ * QKVN;

    // ---- prep ----
    transpose_split<<<dim3(EMBED/32,  EMBED/32), 256>>>(Wq, EMBED, EMBED, wqkvh, wqkvl);
    transpose_split<<<dim3(EMBED/32,  EMBED/32), 256>>>(Wk, EMBED, EMBED,
        wqkvh + (size_t)1024*EMBED, wqkvl + (size_t)1024*EMBED);
    transpose_split<<<dim3(EMBED/32,  EMBED/32), 256>>>(Wv, EMBED, EMBED,
        wqkvh + (size_t)2048*EMBED, wqkvl + (size_t)2048*EMBED);
    transpose_split<<<dim3(EMBED/32,  EMBED/32), 256>>>(Wo, EMBED, EMBED, woh, wol);
    transpose_split<<<dim3(HIDDEN/32, EMBED/32), 256>>>(W1, EMBED, HIDDEN, w1h, w1l);
    transpose_split<<<dim3(EMBED/32,  HIDDEN/32),256>>>(W2, HIDDEN, EMBED, w2h, w2l);
    concat_bias<<<(QKVN + 255)/256, 256>>>(bq, bk, bv, bqkv);
    split_f32<<<(MTOT*EMBED/4 + 255)/256, 256>>>(x, xh, xl, MTOT*EMBED/4);

    // ---- fused QKV: [M,3072] hi/lo ----
    gemm_bb<false><<<dim3(QKVN/128, MTOT/128, 1), 256, SMBB>>>(EMBED,
        xh, xl, EMBED, wqkvh, wqkvl, EMBED, 0, qkvh, qkvl, QKVN, bqkv, 1.f, 0,
        0,0,0,0,0,0, 1, 0);

    // ---- vT per batch from qkv cols 2048+ ----
    transpose_split_hl<<<dim3(EMBED/32, SEQ/32, BATCH), 256>>>(qkvh, qkvl, vth, vtl);

    // ---- energy = (Q@K^T)/8 -> attn fp32 + per-tile softmax stats ----
    gemm_bb<true><<<dim3(SEQ/128, SEQ/128, BATCH*HEADS), 256, SMBB>>>(HDIM,
        qkvh, qkvl, QKVN, qkvh + 1024, qkvl + 1024, QKVN, attn, 0, 0, SEQ,
        0, 0.125f, 0,
        SDQ, HDIM, SDQ, HDIM, (long long)HEADS*SS, SS, HEADS, pst);

    // ---- combine stats ----
    combine_stats<<<NROWS/256, 256>>>(pst, rst);

    // ---- fused softmax-apply + P@V ----
    gemm_pv<<<dim3(1, SEQ/128, BATCH*HEADS), 256, SMPV>>>(attn, rst, vth, vtl, aoh, aol);

    // ---- output projection ----
    gemm_bb<false><<<dim3(EMBED/128, MTOT/128, 1), 256, SMBB>>>(EMBED,
        aoh, aol, EMBED, woh, wol, EMBED, t1, 0, 0, EMBED, bo, 1.f, 0,
        0,0,0,0,0,0, 1, 0);

    // ---- h = LN(x + t1) ----
    add_ln_kernel<<<MTOT, 256>>>(x, t1, gamma, beta, h, hh, hl);

    // ---- MLP ----
    gemm_bb<false><<<dim3(HIDDEN/128, MTOT/128, 1), 256, SMBB>>>(EMBED,
        hh, hl, EMBED, w1h, w1l, EMBED, 0, hidh, hidl, HIDDEN, b1, 1.f, 1,
        0,0,0,0,0,0, 1, 0);
    gemm_bb<false><<<dim3(EMBED/128, MTOT/128, 1), 256, SMBB>>>(HIDDEN,
        hidh, hidl, HIDDEN, w2h, w2l, HIDDEN, mlp, 0, 0, EMBED, b2, 1.f, 0,
        0,0,0,0,0,0, 1, 0);

    // ---- out = LN(mlp + h) ----
    add_ln_kernel<<<MTOT, 256>>>(mlp, h, gamma, beta, out, 0, 0);
}

// round 15
// speedup vs baseline: 1.1361x; 1.1361x over previous
#include <cuda_runtime.h>
#include <cuda_bf16.h>
#include <math.h>
#include <stdint.h>

#define BATCH   2
#define SEQ     2048
#define EMBED   1024
#define HEADS   16
#define HDIM    64
#define HIDDEN  4096
#define MTOT    (BATCH * SEQ)
#define LN_EPS  1e-5f
#define NROWS   (BATCH * HEADS * SEQ)
#define NTILES  (SEQ / 128)

// ------------------------- scratch (device globals) -------------------------
__device__ float g_q  [MTOT * EMBED];
__device__ float g_k  [MTOT * EMBED];
__device__ float g_v  [MTOT * EMBED];
__device__ float g_ao [MTOT * EMBED];
__device__ float g_t1 [MTOT * EMBED];
__device__ float g_h  [MTOT * EMBED];
__device__ float g_hid[(size_t)MTOT * HIDDEN];
__device__ float g_mlp[MTOT * EMBED];
__device__ float2 g_pstats[(size_t)NROWS * NTILES];
__device__ float2 g_rstats[NROWS];

__device__ __nv_bfloat16 g_wq_h[EMBED*EMBED], g_wq_l[EMBED*EMBED];
__device__ __nv_bfloat16 g_wk_h[EMBED*EMBED], g_wk_l[EMBED*EMBED];
__device__ __nv_bfloat16 g_wv_h[EMBED*EMBED], g_wv_l[EMBED*EMBED];
__device__ __nv_bfloat16 g_wo_h[EMBED*EMBED], g_wo_l[EMBED*EMBED];
__device__ __nv_bfloat16 g_w1_h[(size_t)EMBED*HIDDEN], g_w1_l[(size_t)EMBED*HIDDEN];
__device__ __nv_bfloat16 g_w2_h[(size_t)EMBED*HIDDEN], g_w2_l[(size_t)EMBED*HIDDEN];
__device__ __nv_bfloat16 g_vT_h[(size_t)BATCH*EMBED*SEQ], g_vT_l[(size_t)BATCH*EMBED*SEQ];

// ------------------------------- helpers ------------------------------------
__device__ __forceinline__ uint32_t smem_u32(const void* p) {
    uint32_t a;
    asm("{ .reg .u64 t; cvta.to.shared.u64 t, %1; cvt.u32.u64 %0, t; }" : "=r"(a) : "l"(p));
    return a;
}
__device__ __forceinline__ uint32_t sw_off(int row, int kb) {
    uint32_t o = ((uint32_t)(row >> 3) << 10) + ((uint32_t)(row & 7) << 7) + (uint32_t)kb;
    return o ^ ((o >> 3) & 0x70);
}
__device__ __forceinline__ uint32_t b2u(__nv_bfloat162 h) { return *(uint32_t*)&h; }

__device__ __forceinline__ void ldm_x4(uint32_t* r, uint32_t a) {
    asm volatile("ldmatrix.sync.aligned.m8n8.x4.shared.b16 {%0,%1,%2,%3}, [%4];"
                 : "=r"(r[0]), "=r"(r[1]), "=r"(r[2]), "=r"(r[3]) : "r"(a));
}
__device__ __forceinline__ void ldm_x2(uint32_t* r, uint32_t a) {
    asm volatile("ldmatrix.sync.aligned.m8n8.x2.shared.b16 {%0,%1}, [%2];"
                 : "=r"(r[0]), "=r"(r[1]) : "r"(a));
}
__device__ __forceinline__ void mma_bf16(float* c, const uint32_t* a, const uint32_t* b) {
    asm volatile("mma.sync.aligned.m16n8k16.row.col.f32.bf16.bf16.f32 "
                 "{%0,%1,%2,%3}, {%4,%5,%6,%7}, {%8,%9}, {%0,%1,%2,%3};"
                 : "+f"(c[0]), "+f"(c[1]), "+f"(c[2]), "+f"(c[3])
                 : "r"(a[0]), "r"(a[1]), "r"(a[2]), "r"(a[3]), "r"(b[0]), "r"(b[1]));
}
__device__ __forceinline__ void cp_async16(uint32_t dst, const void* src) {
    asm volatile("cp.async.ca.shared.global [%0], [%1], 16;" :: "r"(dst), "l"(src) : "memory");
}
#define CP_COMMIT() asm volatile("cp.async.commit_group;" ::: "memory")
#define CP_WAIT0()  asm volatile("cp.async.wait_group 0;" ::: "memory")

__device__ __forceinline__ float gelu_exact(float x) {
    return 0.5f * x * (1.0f + erff(x * 0.70710678118654752f));
}
__device__ __forceinline__ void split2(float v0, float v1,
                                       __nv_bfloat162& h, __nv_bfloat162& l) {
    h = __floats2bfloat162_rn(v0, v1);
    float2 f = __bfloat1622float2(h);
    l = __floats2bfloat162_rn(v0 - f.x, v1 - f.y);
}

// direct fp32 -> bf16 hi/lo staging
__device__ __forceinline__ void stage_f32(const float* __restrict__ src, int ld,
                                          int k0, char* dst, int rows, int gs, int tid) {
    int iters = (rows * 16) >> 8;
    for (int it = 0; it < iters; it++) {
        int id = it * 256 + tid;
        int row = id >> 4, c4 = (id & 15) << 2;
        float4 v = *(const float4*)(src + (size_t)row * ld + k0 + c4);
        __nv_bfloat162 h01, l01, h23, l23;
        split2(v.x, v.y, h01, l01);
        split2(v.z, v.w, h23, l23);
        uint32_t off = sw_off(row, c4 * 2);
        *(uint2*)(dst + off)      = make_uint2(b2u(h01), b2u(h23));
        *(uint2*)(dst + gs + off) = make_uint2(b2u(l01), b2u(l23));
    }
}

// ---------------------------------------------------------------------------
// R8 warp-tiled bf16x3 mma.sync GEMM + optional STATS epilogue.
//   A: [M,K] fp32 (staged+split in-kernel, register-prefetch double buffer)
//   B: [N,K] fp32 OR presplit bf16 hi/lo
// grid: (N/NT, M/128, nz) ; z decodes (batch, head) via Hn and strides.
// ---------------------------------------------------------------------------
template <int NT, bool STATS>
__global__ void __launch_bounds__(256, 1)
gemm_mma(int K,
         const float* __restrict__ A, int lda,
         const float* __restrict__ Bf,
         const __nv_bfloat16* __restrict__ Bh,
         const __nv_bfloat16* __restrict__ Bl, int ldb,
         float* __restrict__ C, int ldc,
         const float* __restrict__ bias, float alpha, int act,
         long long sAb, long long sAh, long long sBb, long long sBh,
         long long sCb, long long sCh, int Hn,
         float2* __restrict__ pstats)
{
    constexpr int AG  = 16384;
    constexpr int BG  = NT * 128;
    constexpr int ASZ = 2 * AG, BSZ = 2 * BG, BUF = ASZ + BSZ;
    constexpr int WGN = (NT == 128) ? 4 : 2;
    constexpr int WM  = (NT == 128) ? 64 : 32;
    constexpr int MF  = WM / 16;
    constexpr int NF  = 4;

    extern __shared__ char smem[];
    const uint32_t sm32 = smem_u32(smem);
    const int tid = threadIdx.x, wid = tid >> 5, lane = tid & 31;
    const int warp_m = wid / WGN, warp_n = wid % WGN;
    const int wm0 = warp_m * WM, wn0 = warp_n * 32;

    const int bn = blockIdx.x * NT, bm = blockIdx.y * 128;
    const int bb = blockIdx.z / Hn, hh = blockIdx.z % Hn;
    A  += (long long)bb * sAb + (long long)hh * sAh + (long long)bm * lda;
    if (Bf) Bf += (long long)bb * sBb + (long long)hh * sBh + (long long)bn * ldb;
    if (Bh) { long long o = (long long)bb * sBb + (long long)hh * sBh + (long long)bn * ldb;
              Bh += o; Bl += o; }
    C  += (long long)bb * sCb + (long long)hh * sCh;

    const int NC = K >> 6;
    const int a_r = lane & 15, a_k16 = (lane >> 4) << 4;
    const int b_r = lane & 7,  b_k16 = ((lane >> 3) & 1) << 4;

    float acc[MF][NF][4];
#pragma unroll
    for (int mi = 0; mi < MF; mi++)
#pragma unroll
        for (int ni = 0; ni < NF; ni++)
#pragma unroll
            for (int e = 0; e < 4; e++) acc[mi][ni][e] = 0.f;

    // ---- prologue: stage chunk 0 ----
    stage_f32(A, lda, 0, smem, 128, AG, tid);
    if (Bf) {
        stage_f32(Bf, ldb, 0, smem + ASZ, NT, BG, tid);
    } else {
#pragma unroll
        for (int g = 0; g < 2; g++) {
            const __nv_bfloat16* src = g ? Bl : Bh;
            for (int it = 0; it < NT / 32; it++) {
                int id = it * 256 + tid;
                int row = id >> 3, u = id & 7;
                cp_async16(sm32 + ASZ + g * BG + sw_off(row, u * 16),
                           src + (size_t)row * ldb + u * 8);
            }
        }
        CP_COMMIT(); CP_WAIT0();
    }
    __syncthreads();

    float4 pf[8];
    for (int c = 0; c < NC; c++) {
        const int buf = c & 1;
        const uint32_t sA = sm32 + buf * BUF;
        const uint32_t sB = sA + ASZ;
        char* nxt = smem + (buf ^ 1) * BUF;
        const bool more = (c + 1 < NC);

        if (more) {
            const int k0 = (c + 1) << 6;
#pragma unroll
            for (int i = 0; i < 8; i++) {
                int id = i * 256 + tid;
                int row = id >> 4, c4 = (id & 15) << 2;
                pf[i] = *(const float4*)(A + (size_t)row * lda + k0 + c4);
            }
            if (!Bf) {
#pragma unroll
                for (int g = 0; g < 2; g++) {
                    const __nv_bfloat16* src = g ? Bl : Bh;
                    for (int it = 0; it < NT / 32; it++) {
                        int id = it * 256 + tid;
                        int row = id >> 3, u = id & 7;
                        cp_async16(smem_u32(nxt) + ASZ + g * BG + sw_off(row, u * 16),
                                   src + (size_t)row * ldb + k0 + u * 8);
                    }
                }
                CP_COMMIT();
            }
        }

#pragma unroll
        for (int ks = 0; ks < 4; ks++) {
            uint32_t ah[MF][4], al[MF][4], bh[NF][2], bl[NF][2];
#pragma unroll
            for (int mi = 0; mi < MF; mi++) {
                uint32_t off = sw_off(wm0 + mi * 16 + a_r, ks * 32 + a_k16);
                ldm_x4(ah[mi], sA + off);
                ldm_x4(al[mi], sA + AG + off);
            }
#pragma unroll
            for (int ni = 0; ni < NF; ni++) {
                uint32_t off = sw_off(wn0 + ni * 8 + b_r, ks * 32 + b_k16);
                ldm_x2(bh[ni], sB + off);
                ldm_x2(bl[ni], sB + BG + off);
            }
#pragma unroll
            for (int mi = 0; mi < MF; mi++)
#pragma unroll
                for (int ni = 0; ni < NF; ni++) {
                    mma_bf16(acc[mi][ni], ah[mi], bh[ni]);
                    mma_bf16(acc[mi][ni], ah[mi], bl[ni]);
                    mma_bf16(acc[mi][ni], al[mi], bh[ni]);
                }
        }

        if (more) {
#pragma unroll
            for (int i = 0; i < 8; i++) {
                int id = i * 256 + tid;
                int row = id >> 4, c4 = (id & 15) << 2;
                float4 v = pf[i];
                __nv_bfloat162 h01, l01, h23, l23;
                split2(v.x, v.y, h01, l01);
                split2(v.z, v.w, h23, l23);
                uint32_t off = sw_off(row, c4 * 2);
                *(uint2*)(nxt + off)      = make_uint2(b2u(h01), b2u(h23));
                *(uint2*)(nxt + AG + off) = make_uint2(b2u(l01), b2u(l23));
            }
            if (Bf) stage_f32(Bf, ldb, (c + 1) << 6, nxt + ASZ, NT, BG, tid);
            else    CP_WAIT0();
        }
        __syncthreads();
    }

    // ---- epilogue: regs -> gmem, fused alpha/bias/gelu ----
#pragma unroll
    for (int mi = 0; mi < MF; mi++) {
        const int r0 = bm + wm0 + mi * 16 + (lane >> 2);
#pragma unroll
        for (int ni = 0; ni < NF; ni++) {
            const int cb = bn + wn0 + ni * 8 + (lane & 3) * 2;
            float b0 = bias ? bias[cb] : 0.f, b1 = bias ? bias[cb + 1] : 0.f;
            float v0 = acc[mi][ni][0] * alpha + b0;
            float v1 = acc[mi][ni][1] * alpha + b1;
            float v2 = acc[mi][ni][2] * alpha + b0;
            float v3 = acc[mi][ni][3] * alpha + b1;
            if (act) { v0 = gelu_exact(v0); v1 = gelu_exact(v1);
                       v2 = gelu_exact(v2); v3 = gelu_exact(v3); }
            *(float2*)(C + (size_t)r0 * ldc + cb)       = make_float2(v0, v1);
            *(float2*)(C + (size_t)(r0 + 8) * ldc + cb) = make_float2(v2, v3);
        }
    }

    // ---- STATS epilogue (energy only, NT=128) ----
    if constexpr (STATS) {
        __syncthreads();
        float* smaxw = (float*)smem;          // [4][128]
        float* ssumw = (float*)smem + 512;    // [4][128]
        float* rowmx = (float*)smem + 1024;   // [128]
#pragma unroll
        for (int mi = 0; mi < MF; mi++)
#pragma unroll
            for (int rr = 0; rr < 2; rr++) {
                int row = wm0 + mi * 16 + (lane >> 2) + rr * 8;
                float mx = -1e30f;
#pragma unroll
                for (int ni = 0; ni < NF; ni++) {
                    mx = fmaxf(mx, acc[mi][ni][rr * 2]     * alpha);
                    mx = fmaxf(mx, acc[mi][ni][rr * 2 + 1] * alpha);
                }
                mx = fmaxf(mx, __shfl_xor_sync(0xffffffffu, mx, 1));
                mx = fmaxf(mx, __shfl_xor_sync(0xffffffffu, mx, 2));
                if ((lane & 3) == 0) smaxw[warp_n * 128 + row] = mx;
            }
        __syncthreads();
        if (tid < 128) {
            rowmx[tid] = fmaxf(fmaxf(smaxw[tid], smaxw[128 + tid]),
                               fmaxf(smaxw[256 + tid], smaxw[384 + tid]));
        }
        __syncthreads();
#pragma unroll
        for (int mi = 0; mi < MF; mi++)
#pragma unroll
            for (int rr = 0; rr < 2; rr++) {
                int row = wm0 + mi * 16 + (lane >> 2) + rr * 8;
                float m = rowmx[row], s = 0.f;
#pragma unroll
                for (int ni = 0; ni < NF; ni++) {
                    s += __expf(acc[mi][ni][rr * 2]     * alpha - m);
                    s += __expf(acc[mi][ni][rr * 2 + 1] * alpha - m);
                }
                s += __shfl_xor_sync(0xffffffffu, s, 1);
                s += __shfl_xor_sync(0xffffffffu, s, 2);
                if ((lane & 3) == 0) ssumw[warp_n * 128 + row] = s;
            }
        __syncthreads();
        if (tid < 128) {
            float s = ssumw[tid] + ssumw[128 + tid] + ssumw[256 + tid] + ssumw[384 + tid];
            pstats[((long long)blockIdx.z * SEQ + bm + tid) * NTILES + blockIdx.x] =
                make_float2(rowmx[tid], s);
        }
    }
}

// ---- combine per-tile stats -> per-row (M, 1/S) -----------------------------
__global__ void __launch_bounds__(256)
combine_stats(const float2* __restrict__ ps, float2* __restrict__ rs)
{
    int r = blockIdx.x * 256 + threadIdx.x;
    if (r >= NROWS) return;
    const float2* p = ps + (size_t)r * NTILES;
    float M = -1e30f;
    float2 t[NTILES];
#pragma unroll
    for (int i = 0; i < NTILES; i++) { t[i] = p[i]; M = fmaxf(M, t[i].x); }
    float S = 0.f;
#pragma unroll
    for (int i = 0; i < NTILES; i++) S += t[i].y * __expf(t[i].x - M);
    rs[r] = make_float2(M, 1.0f / S);
}

// ---------------------------------------------------------------------------
// Fused softmax-apply + P@V (R8 attn@V structure).  Reads E fp32 (attn
// slice), writes P in place, ao = P @ vT^T -> fp32.  grid (1, SEQ/128, B*H).
// ---------------------------------------------------------------------------
__global__ void __launch_bounds__(256, 1)
gemm_pv(float* __restrict__ E_all, const float2* __restrict__ rs_all,
        const __nv_bfloat16* __restrict__ Vh_all, const __nv_bfloat16* __restrict__ Vl_all,
        float* __restrict__ ao)
{
    constexpr int AG = 16384, ASZ = 32768, BG = 8192, BUF = ASZ + 2 * BG;
    constexpr int MF = 2, NF = 4;

    extern __shared__ char smem[];
    const uint32_t sm32 = smem_u32(smem);
    const int tid = threadIdx.x, wid = tid >> 5, lane = tid & 31;
    const int warp_m = wid >> 1, warp_n = wid & 1;
    const int wm0 = warp_m * 32, wn0 = warp_n * 32;

    const int bm = blockIdx.y * 128;
    const int z = blockIdx.z, bb = z >> 4, hh = z & 15;
    float* E = E_all + (long long)z * SEQ * SEQ + (long long)bm * SEQ;
    const float2* rs = rs_all + (long long)z * SEQ + bm;
    const size_t vo = (size_t)bb * EMBED * SEQ + (size_t)hh * HDIM * SEQ;
    const __nv_bfloat16* Bh = Vh_all + vo;
    const __nv_bfloat16* Bl = Vl_all + vo;

    float2 ms[8];
#pragma unroll
    for (int it = 0; it < 8; it++) ms[it] = rs[(it * 256 + tid) >> 4];

    const int a_r = lane & 15, a_k16 = (lane >> 4) << 4;
    const int b_r = lane & 7,  b_k16 = ((lane >> 3) & 1) << 4;

    float acc[MF][NF][4];
#pragma unroll
    for (int mi = 0; mi < MF; mi++)
#pragma unroll
        for (int ni = 0; ni < NF; ni++)
#pragma unroll
            for (int e = 0; e < 4; e++) acc[mi][ni][e] = 0.f;

    auto issueB = [&](int c, int s) {
        const int k0 = c << 6;
        const uint32_t st = sm32 + s * BUF + ASZ;
#pragma unroll
        for (int it = 0; it < 2; it++) {
            int id = it * 256 + tid;
            int row = id >> 3, u = id & 7;
            uint32_t o = sw_off(row, u * 16);
            const size_t sidx = (size_t)row * SEQ + k0 + u * 8;
            cp_async16(st + o,      Bh + sidx);
            cp_async16(st + BG + o, Bl + sidx);
        }
    };
    // convert E values -> P (write back) -> smem hi/lo
    auto stageE = [&](int k0, char* dst, const float4* pf, bool fromPf) {
#pragma unroll
        for (int it = 0; it < 8; it++) {
            int id = it * 256 + tid;
            int row = id >> 4, c4 = (id & 15) << 2;
            float4 e = fromPf ? pf[it] : *(const float4*)(E + (size_t)row * SEQ + k0 + c4);
            const float M = ms[it].x, IS = ms[it].y;
            float4 p;
            p.x = __expf(e.x - M) * IS;
            p.y = __expf(e.y - M) * IS;
            p.z = __expf(e.z - M) * IS;
            p.w = __expf(e.w - M) * IS;
            *(float4*)(E + (size_t)row * SEQ + k0 + c4) = p;
            __nv_bfloat162 h0, l0, h1, l1;
            split2(p.x, p.y, h0, l0);
            split2(p.z, p.w, h1, l1);
            uint32_t off = sw_off(row, c4 * 2);
            *(uint2*)(dst + off)      = make_uint2(b2u(h0), b2u(h1));
            *(uint2*)(dst + AG + off) = make_uint2(b2u(l0), b2u(l1));
        }
    };

    issueB(0, 0);
    CP_COMMIT();
    stageE(0, smem, nullptr, false);
    CP_WAIT0();
    __syncthreads();

    constexpr int NC = SEQ >> 6;   // 32
    float4 pf[8];
    for (int c = 0; c < NC; c++) {
        const int buf = c & 1;
        char* nxt = smem + (buf ^ 1) * BUF;
        const bool more = (c + 1 < NC);

        if (more) {
            issueB(c + 1, buf ^ 1);
            CP_COMMIT();
            const int k0 = (c + 1) << 6;
#pragma unroll
            for (int it = 0; it < 8; it++) {
                int id = it * 256 + tid;
                int row = id >> 4, c4 = (id & 15) << 2;
                pf[it] = *(const float4*)(E + (size_t)row * SEQ + k0 + c4);
            }
        }

        const uint32_t sA = sm32 + buf * BUF;
        const uint32_t sB = sA + ASZ;
#pragma unroll
        for (int ks = 0; ks < 4; ks++) {
            uint32_t ah[MF][4], al[MF][4], bh[NF][2], bl[NF][2];
#pragma unroll
            for (int mi = 0; mi < MF; mi++) {
                uint32_t off = sw_off(wm0 + mi * 16 + a_r, ks * 32 + a_k16);
                ldm_x4(ah[mi], sA + off);
                ldm_x4(al[mi], sA + AG + off);
            }
#pragma unroll
            for (int ni = 0; ni < NF; ni++) {
                uint32_t off = sw_off(wn0 + ni * 8 + b_r, ks * 32 + b_k16);
                ldm_x2(bh[ni], sB + off);
                ldm_x2(bl[ni], sB + BG + off);
            }
#pragma unroll
            for (int mi = 0; mi < MF; mi++)
#pragma unroll
                for (int ni = 0; ni < NF; ni++) {
                    mma_bf16(acc[mi][ni], ah[mi], bh[ni]);
                    mma_bf16(acc[mi][ni], ah[mi], bl[ni]);
                    mma_bf16(acc[mi][ni], al[mi], bh[ni]);
                }
        }

        if (more) {
            stageE((c + 1) << 6, nxt, pf, true);
            CP_WAIT0();
        }
        __syncthreads();
    }

    // epilogue: ao fp32
#pragma unroll
    for (int mi = 0; mi < MF; mi++) {
        const int gr = bm + wm0 + mi * 16 + (lane >> 2);
#pragma unroll
        for (int ni = 0; ni < NF; ni++) {
            const int cb = wn0 + ni * 8 + (lane & 3) * 2;
            const size_t i0 = ((size_t)bb * SEQ + gr)     * EMBED + hh * HDIM + cb;
            const size_t i1 = ((size_t)bb * SEQ + gr + 8) * EMBED + hh * HDIM + cb;
            *(float2*)(ao + i0) = make_float2(acc[mi][ni][0], acc[mi][ni][1]);
            *(float2*)(ao + i1) = make_float2(acc[mi][ni][2], acc[mi][ni][3]);
        }
    }
}

// -------- transpose + split:  in [K][N] fp32  ->  out [N][K] bf16 hi/lo -----
__global__ void __launch_bounds__(256)
transpose_split(const float* __restrict__ in, int K, int N,
                __nv_bfloat16* __restrict__ oh, __nv_bfloat16* __restrict__ ol)
{
    __shared__ float tb[32][33];
    const int n0 = blockIdx.x * 32, k0 = blockIdx.y * 32;
    const int tx = threadIdx.x & 31, ty = threadIdx.x >> 5;
    for (int j = ty; j < 32; j += 8)
        tb[j][tx] = in[(size_t)(k0 + j) * N + n0 + tx];
    __syncthreads();
    for (int j = ty; j < 32; j += 8) {
        float v = tb[tx][j];
        __nv_bfloat16 h = __float2bfloat16(v);
        __nv_bfloat16 l = __float2bfloat16(v - __bfloat162float(h));
        size_t o = (size_t)(n0 + j) * K + k0 + tx;
        oh[o] = h; ol[o] = l;
    }
}

// ------------------------------ add + LN ------------------------------------
__global__ void __launch_bounds__(256)
add_ln_kernel(const float* __restrict__ a, const float* __restrict__ b,
              const float* __restrict__ gamma, const float* __restrict__ beta,
              float* __restrict__ out)
{
    const long long base = (long long)blockIdx.x * EMBED;
    const int tid = threadIdx.x, lane = tid & 31, wid = tid >> 5;
    float v[4], s1 = 0.f, s2 = 0.f;
#pragma unroll
    for (int i = 0; i < 4; i++) {
        int col = i * 256 + tid;
        float x = a[base + col] + b[base + col];
        v[i] = x; s1 += x; s2 += x * x;
    }
#pragma unroll
    for (int o = 16; o; o >>= 1) {
        s1 += __shfl_xor_sync(0xffffffffu, s1, o);
        s2 += __shfl_xor_sync(0xffffffffu, s2, o);
    }
    __shared__ float r1[8], r2[8];
    if (lane == 0) { r1[wid] = s1; r2[wid] = s2; }
    __syncthreads();
    float t1 = 0.f, t2 = 0.f;
#pragma unroll
    for (int i = 0; i < 8; i++) { t1 += r1[i]; t2 += r2[i]; }
    float mu = t1 * (1.0f / EMBED);
    float var = t2 * (1.0f / EMBED) - mu * mu;
    float inv = rsqrtf(var + LN_EPS);
#pragma unroll
    for (int i = 0; i < 4; i++) {
        int col = i * 256 + tid;
        out[base + col] = (v[i] - mu) * inv * gamma[col] + beta[col];
    }
}

// ------------------------------- launcher -----------------------------------
extern "C" void kernel_launch(void* const* d_in, const int* in_sizes, int n_in,
                              void* d_out, int out_size)
{
    const float* x  = (const float*)d_in[0];
    const float* Wq = (const float*)d_in[1];  const float* bq = (const float*)d_in[2];
    const float* Wk = (const float*)d_in[3];  const float* bk = (const float*)d_in[4];
    const float* Wv = (const float*)d_in[5];  const float* bv = (const float*)d_in[6];
    const float* Wo = (const float*)d_in[7];  const float* bo = (const float*)d_in[8];
    const float* W1 = (const float*)d_in[9];  const float* b1 = (const float*)d_in[10];
    const float* W2 = (const float*)d_in[11]; const float* b2 = (const float*)d_in[12];
    const float* gamma = (const float*)d_in[13];
    const float* beta  = (const float*)d_in[14];

    float* out  = (float*)d_out;
    float* attn = out + (long long)MTOT * EMBED;

    float *q, *k, *v, *ao, *t1, *h, *hid, *mlp;
    cudaGetSymbolAddress((void**)&q,   g_q);
    cudaGetSymbolAddress((void**)&k,   g_k);
    cudaGetSymbolAddress((void**)&v,   g_v);
    cudaGetSymbolAddress((void**)&ao,  g_ao);
    cudaGetSymbolAddress((void**)&t1,  g_t1);
    cudaGetSymbolAddress((void**)&h,   g_h);
    cudaGetSymbolAddress((void**)&hid, g_hid);
    cudaGetSymbolAddress((void**)&mlp, g_mlp);

    float2 *pst, *rst;
    cudaGetSymbolAddress((void**)&pst, g_pstats);
    cudaGetSymbolAddress((void**)&rst, g_rstats);

    __nv_bfloat16 *wqh,*wql,*wkh,*wkl,*wvh,*wvl,*woh,*wol,*w1h,*w1l,*w2h,*w2l,*vth,*vtl;
    cudaGetSymbolAddress((void**)&wqh, g_wq_h); cudaGetSymbolAddress((void**)&wql, g_wq_l);
    cudaGetSymbolAddress((void**)&wkh, g_wk_h); cudaGetSymbolAddress((void**)&wkl, g_wk_l);
    cudaGetSymbolAddress((void**)&wvh, g_wv_h); cudaGetSymbolAddress((void**)&wvl, g_wv_l);
    cudaGetSymbolAddress((void**)&woh, g_wo_h); cudaGetSymbolAddress((void**)&wol, g_wo_l);
    cudaGetSymbolAddress((void**)&w1h, g_w1_h); cudaGetSymbolAddress((void**)&w1l, g_w1_l);
    cudaGetSymbolAddress((void**)&w2h, g_w2_h); cudaGetSymbolAddress((void**)&w2l, g_w2_l);
    cudaGetSymbolAddress((void**)&vth, g_vT_h); cudaGetSymbolAddress((void**)&vtl, g_vT_l);

    const int SM128 = 2 * (32768 + 2 * 128 * 128);   // 131072
    const int SMPV  = 2 * (32768 + 2 * 64  * 128);   // 98304
    cudaFuncSetAttribute(gemm_mma<128,false>, cudaFuncAttributeMaxDynamicSharedMemorySize, SM128);
    cudaFuncSetAttribute(gemm_mma<128,true>,  cudaFuncAttributeMaxDynamicSharedMemorySize, SM128);
    cudaFuncSetAttribute(gemm_pv,             cudaFuncAttributeMaxDynamicSharedMemorySize, SMPV);

    const long long SD = (long long)SEQ * EMBED;
    const long long SS = (long long)SEQ * SEQ;

    // weight prep: [K][N] -> [N][K] bf16 hi/lo
    transpose_split<<<dim3(EMBED/32,  EMBED/32), 256>>>(Wq, EMBED, EMBED, wqh, wql);
    transpose_split<<<dim3(EMBED/32,  EMBED/32), 256>>>(Wk, EMBED, EMBED, wkh, wkl);
    transpose_split<<<dim3(EMBED/32,  EMBED/32), 256>>>(Wv, EMBED, EMBED, wvh, wvl);
    transpose_split<<<dim3(EMBED/32,  EMBED/32), 256>>>(Wo, EMBED, EMBED, woh, wol);
    transpose_split<<<dim3(HIDDEN/32, EMBED/32), 256>>>(W1, EMBED, HIDDEN, w1h, w1l);
    transpose_split<<<dim3(EMBED/32,  HIDDEN/32),256>>>(W2, HIDDEN, EMBED, w2h, w2l);

    // QKV projections (A = x fp32, staged in-kernel)
    gemm_mma<128,false><<<dim3(EMBED/128, MTOT/128, 1), 256, SM128>>>(EMBED,
        x, EMBED, 0, wqh, wql, EMBED, q, EMBED, bq, 1.f, 0, 0,0,0,0,0,0, 1, 0);
    gemm_mma<128,false><<<dim3(EMBED/128, MTOT/128, 1), 256, SM128>>>(EMBED,
        x, EMBED, 0, wkh, wkl, EMBED, k, EMBED, bk, 1.f, 0, 0,0,0,0,0,0, 1, 0);
    gemm_mma<128,false><<<dim3(EMBED/128, MTOT/128, 1), 256, SM128>>>(EMBED,
        x, EMBED, 0, wvh, wvl, EMBED, v, EMBED, bv, 1.f, 0, 0,0,0,0,0,0, 1, 0);

    // vT per batch: [S][D] -> [D][S] bf16 hi/lo
    transpose_split<<<dim3(EMBED/32, SEQ/32), 256>>>(v,      SEQ, EMBED, vth, vtl);
    transpose_split<<<dim3(EMBED/32, SEQ/32), 256>>>(v + SD, SEQ, EMBED,
        vth + (size_t)EMBED*SEQ, vtl + (size_t)EMBED*SEQ);

    // energy = (Q @ K^T)/8 -> attn fp32 + per-tile softmax stats
    gemm_mma<128,true><<<dim3(SEQ/128, SEQ/128, BATCH*HEADS), 256, SM128>>>(HDIM,
        q, EMBED, k, 0, 0, EMBED, attn, SEQ, 0, 0.125f, 0,
        SD, HDIM, SD, HDIM, (long long)HEADS*SS, SS, HEADS, pst);

    // combine stats
    combine_stats<<<NROWS/256, 256>>>(pst, rst);

    // fused softmax-apply + P@V  (writes P in place, ao fp32)
    gemm_pv<<<dim3(1, SEQ/128, BATCH*HEADS), 256, SMPV>>>(attn, rst, vth, vtl, ao);

    // output projection (A = ao fp32)
    gemm_mma<128,false><<<dim3(EMBED/128, MTOT/128, 1), 256, SM128>>>(EMBED,
        ao, EMBED, 0, woh, wol, EMBED, t1, EMBED, bo, 1.f, 0, 0,0,0,0,0,0, 1, 0);

    add_ln_kernel<<<MTOT, 256>>>(x, t1, gamma, beta, h);

    // MLP
    gemm_mma<128,false><<<dim3(HIDDEN/128, MTOT/128, 1), 256, SM128>>>(EMBED,
        h, EMBED, 0, w1h, w1l, EMBED, hid, HIDDEN, b1, 1.f, 1, 0,0,0,0,0,0, 1, 0);
    gemm_mma<128,false><<<dim3(EMBED/128, MTOT/128, 1), 256, SM128>>>(HIDDEN,
        hid, HIDDEN, 0, w2h, w2l, HIDDEN, mlp, EMBED, b2, 1.f, 0, 0,0,0,0,0,0, 1, 0);

    add_ln_kernel<<<MTOT, 256>>>(mlp, h, gamma, beta, out);
}